// round 14
// baseline (speedup 1.0000x reference)
#include <cuda_runtime.h>
#include <cuda_fp16.h>
#include <cstdint>

#define IN_F   4096
#define OUT_F  4096
#define LORA_R 64
#define M_TOTAL 8192

// ---------------- device scratch ----------------
__device__ __half g_xf[(size_t)M_TOTAL * IN_F];    // fp16(s*x)  64 MB
__device__ __half g_wf[(size_t)OUT_F * IN_F];      // fp16(Wq)   32 MB (exact)
__device__ __half g_bf[(size_t)OUT_F * LORA_R];    // fp16(lora_B)
__device__ __half g_t[(size_t)M_TOTAL * LORA_R];   // fp16(0.25 * x @ A^T)

__device__ __forceinline__ uint32_t smem_u32(const void* p) {
    uint32_t a;
    asm("{ .reg .u64 t; cvta.to.shared.u64 t, %1; cvt.u32.u64 %0, t; }" : "=r"(a) : "l"(p));
    return a;
}

// ---------------- mma helpers ----------------
__device__ __forceinline__ void cp16(uint32_t dst, const void* src) {
    asm volatile("cp.async.cg.shared.global [%0], [%1], 16;" :: "r"(dst), "l"(src) : "memory");
}
__device__ __forceinline__ void ldmx4(uint32_t addr, uint32_t& r0, uint32_t& r1,
                                      uint32_t& r2, uint32_t& r3) {
    asm volatile("ldmatrix.sync.aligned.m8n8.x4.shared.b16 {%0,%1,%2,%3}, [%4];"
                 : "=r"(r0), "=r"(r1), "=r"(r2), "=r"(r3) : "r"(addr));
}
__device__ __forceinline__ void mma16816(float* c, const uint32_t* a, const uint32_t* b) {
    asm volatile(
        "mma.sync.aligned.m16n8k16.row.col.f32.f16.f16.f32 "
        "{%0,%1,%2,%3}, {%4,%5,%6,%7}, {%8,%9}, {%0,%1,%2,%3};"
        : "+f"(c[0]), "+f"(c[1]), "+f"(c[2]), "+f"(c[3])
        : "r"(a[0]), "r"(a[1]), "r"(a[2]), "r"(a[3]), "r"(b[0]), "r"(b[1]));
}

// ---------------- kernel 1: fused t-compute + conversions (128 threads) ----------
// blocks [0, TB):              t = 0.25 * x @ A^T   (fp16 mma, fp32 sources)
// blocks [TB, TB+XB):          x  -> fp16(s*x)
// blocks [TB+XB, TB+XB+WB):    Wq -> fp16 (per-block int32/int8 detect)
// blocks [TB+XB+WB, ...):      lora_B -> fp16
#define TB  (M_TOTAL / 64)                    // 128
#define XB  (M_TOTAL * IN_F / 4 / 128)        // 65536
#define WB  (OUT_F * IN_F / 4 / 128)          // 32768
#define BB  (OUT_F * LORA_R / 4 / 128)        // 512
#define TSTR 40

__global__ __launch_bounds__(128) void prep_kernel(
    const float* __restrict__ x, const void* __restrict__ wqv,
    const float* __restrict__ A, const float* __restrict__ B,
    const float* __restrict__ ws)
{
    const int b = blockIdx.x;
    const int tid = threadIdx.x;

    if (b < TB) {
        // ---- t-block: CTA 64(M) x 64(R), BK=32, 4 warps (2m x 2n), warp 32x32 ----
        __shared__ __align__(16) __half sm[(64 + 64) * TSTR];
        const int wid = tid >> 5, lane = tid & 31;
        const int warp_m = wid & 1, warp_n = wid >> 1;
        const int bm = b;

        float acc[2][4][4];
#pragma unroll
        for (int i = 0; i < 2; ++i)
#pragma unroll
            for (int j = 0; j < 4; ++j)
#pragma unroll
                for (int r = 0; r < 4; ++r) acc[i][j][r] = 0.f;

        // per-thread: 4 float4 of x-tile + 4 float4 of A-tile (64x32 fp32 each)
        // chunk c (0..511): row = c>>3, col8 = (c&7)*4 floats... use 512 fp32-float4
        // chunks per matrix -> 4/thread.
        const int rowA = warp_m * 32 + (lane & 15);
        const int rowW = warp_n * 32 + (lane & 7) + ((lane >> 3) & 1) * 8;
        const int koff = (lane >> 4) * 8;
        const uint32_t bX = smem_u32(sm);
        const uint32_t bAa = bX + (uint32_t)(64 * TSTR) * 2;

        float4 vx[4], va[4];
        // prefetch k-tile 0
#pragma unroll
        for (int u = 0; u < 4; ++u) {
            int c = tid + u * 128;
            int row = c >> 3, cc = c & 7;
            vx[u] = *reinterpret_cast<const float4*>(
                x + (size_t)(bm * 64 + row) * IN_F + cc * 4);
            va[u] = *reinterpret_cast<const float4*>(
                A + (size_t)row * IN_F + cc * 4);
        }

        for (int kt = 0; kt < IN_F / 32; ++kt) {
            // store current regs -> smem (fp16)
#pragma unroll
            for (int u = 0; u < 4; ++u) {
                int c = tid + u * 128;
                int row = c >> 3, cc = c & 7;
                __half2* px = reinterpret_cast<__half2*>(sm) +
                              (row * TSTR + cc * 4) / 2;
                px[0] = __floats2half2_rn(vx[u].x, vx[u].y);
                px[1] = __floats2half2_rn(vx[u].z, vx[u].w);
                __half2* pa = reinterpret_cast<__half2*>(sm + 64 * TSTR) +
                              (row * TSTR + cc * 4) / 2;
                pa[0] = __floats2half2_rn(va[u].x, va[u].y);
                pa[1] = __floats2half2_rn(va[u].z, va[u].w);
            }
            __syncthreads();
            // prefetch next tile while mma consumes smem
            if (kt + 1 < IN_F / 32) {
                const int ko = (kt + 1) * 32;
#pragma unroll
                for (int u = 0; u < 4; ++u) {
                    int c = tid + u * 128;
                    int row = c >> 3, cc = c & 7;
                    vx[u] = *reinterpret_cast<const float4*>(
                        x + (size_t)(bm * 64 + row) * IN_F + ko + cc * 4);
                    va[u] = *reinterpret_cast<const float4*>(
                        A + (size_t)row * IN_F + ko + cc * 4);
                }
            }
#pragma unroll
            for (int ks = 0; ks < 2; ++ks) {
                const int kb = ks * 16 + koff;
                uint32_t af[2][4], bf[4][2];
#pragma unroll
                for (int mf = 0; mf < 2; ++mf)
                    ldmx4(bX + (uint32_t)((rowA + mf * 16) * TSTR + kb) * 2,
                          af[mf][0], af[mf][1], af[mf][2], af[mf][3]);
#pragma unroll
                for (int nf2 = 0; nf2 < 2; ++nf2) {
                    uint32_t r0, r1, r2, r3;
                    ldmx4(bAa + (uint32_t)((rowW + nf2 * 16) * TSTR + kb) * 2,
                          r0, r1, r2, r3);
                    bf[nf2 * 2 + 0][0] = r0; bf[nf2 * 2 + 0][1] = r2;
                    bf[nf2 * 2 + 1][0] = r1; bf[nf2 * 2 + 1][1] = r3;
                }
#pragma unroll
                for (int mf = 0; mf < 2; ++mf)
#pragma unroll
                    for (int nf = 0; nf < 4; ++nf)
                        mma16816(acc[mf][nf], af[mf], bf[nf]);
            }
            __syncthreads();
        }

        const int g = lane >> 2, t4 = lane & 3;
#pragma unroll
        for (int mf = 0; mf < 2; ++mf)
#pragma unroll
            for (int nf = 0; nf < 4; ++nf) {
                int m = bm * 64 + warp_m * 32 + mf * 16 + g;
                int n = warp_n * 32 + nf * 8 + t4 * 2;
                *reinterpret_cast<__half2*>(g_t + (size_t)m * LORA_R + n) =
                    __floats2half2_rn(0.25f * acc[mf][nf][0], 0.25f * acc[mf][nf][1]);
                *reinterpret_cast<__half2*>(g_t + (size_t)(m + 8) * LORA_R + n) =
                    __floats2half2_rn(0.25f * acc[mf][nf][2], 0.25f * acc[mf][nf][3]);
            }
    } else if (b < TB + XB) {
        const float s = ws[0];
        size_t i = (size_t)(b - TB) * 128 + tid;
        float4 v = reinterpret_cast<const float4*>(x)[i];
        __half2* p = reinterpret_cast<__half2*>(g_xf) + i * 2;
        p[0] = __floats2half2_rn(s * v.x, s * v.y);
        p[1] = __floats2half2_rn(s * v.z, s * v.w);
    } else if (b < TB + XB + WB) {
        __shared__ int s_is_i32;
        size_t i = ((size_t)(b - TB - XB) * 128 + tid) * 4;
        int4 q = *reinterpret_cast<const int4*>((const int*)wqv + i);
        bool ok = (q.x >= -8 && q.x <= 7) && (q.y >= -8 && q.y <= 7) &&
                  (q.z >= -8 && q.z <= 7) && (q.w >= -8 && q.w <= 7);
        if (tid == 0) s_is_i32 = 1;
        __syncthreads();
        if (!ok) s_is_i32 = 0;
        __syncthreads();
        __half2* p = reinterpret_cast<__half2*>(g_wf + i);
        if (s_is_i32) {
            p[0] = __floats2half2_rn((float)q.x, (float)q.y);
            p[1] = __floats2half2_rn((float)q.z, (float)q.w);
        } else {
            const int8_t* c = (const int8_t*)wqv + i;
            p[0] = __floats2half2_rn((float)c[0], (float)c[1]);
            p[1] = __floats2half2_rn((float)c[2], (float)c[3]);
        }
    } else {
        size_t i = ((size_t)(b - TB - XB - WB) * 128 + tid) * 4;
        float4 v = *reinterpret_cast<const float4*>(B + i);
        __half2* p = reinterpret_cast<__half2*>(g_bf + i);
        p[0] = __floats2half2_rn(v.x, v.y);
        p[1] = __floats2half2_rn(v.z, v.w);
    }
}

// ---------------- kernel 2: main fp16 mma GEMM (unchanged, at HMMA ceiling) ----------
#define SSTR 72
#define NTILES (IN_F / 64 + 1)           // 65
#define A_ROWS 256
#define W_ROWS 128
#define STAGE_H ((A_ROWS + W_ROWS) * SSTR)
#define STAGES 3
#define SMEM_MAIN (STAGES * STAGE_H * 2)  // 165888 B

__global__ __launch_bounds__(256, 1) void qlora_mma_kernel(float* __restrict__ out)
{
    extern __shared__ __align__(16) __half smem[];

    const int tid  = threadIdx.x;
    const int wid  = tid >> 5;
    const int lane = tid & 31;
    const int warp_m = wid & 3;
    const int warp_n = wid >> 2;
    const int bm = blockIdx.y, bn = blockIdx.x;
    const uint32_t sbase = smem_u32(smem);

    float acc[4][8][4];
#pragma unroll
    for (int i = 0; i < 4; ++i)
#pragma unroll
        for (int j = 0; j < 8; ++j)
#pragma unroll
            for (int r = 0; r < 4; ++r) acc[i][j][r] = 0.f;

    auto issue = [&](int kt) {
        if (kt < NTILES) {
            const int s = kt % STAGES;
            const __half *aSrc, *wSrc;
            int lda, ko;
            if (kt < IN_F / 64) { aSrc = g_xf; wSrc = g_wf; lda = IN_F;   ko = kt * 64; }
            else                { aSrc = g_t;  wSrc = g_bf; lda = LORA_R; ko = 0; }
            const __half* aBase = aSrc + (size_t)(bm * A_ROWS) * lda + ko;
            const __half* wBase = wSrc + (size_t)(bn * W_ROWS) * lda + ko;
            const uint32_t dA = sbase + (uint32_t)(s * STAGE_H) * 2;
            const uint32_t dW = dA + (uint32_t)(A_ROWS * SSTR) * 2;
#pragma unroll
            for (int u = 0; u < 8; ++u) {
                int c = tid + u * 256;
                int row = c >> 3, kc = (c & 7) * 8;
                cp16(dA + (uint32_t)(row * SSTR + kc) * 2, aBase + (size_t)row * lda + kc);
            }
#pragma unroll
            for (int u = 0; u < 4; ++u) {
                int c = tid + u * 256;
                int row = c >> 3, kc = (c & 7) * 8;
                cp16(dW + (uint32_t)(row * SSTR + kc) * 2, wBase + (size_t)row * lda + kc);
            }
        }
        asm volatile("cp.async.commit_group;" ::: "memory");
    };

    issue(0); issue(1);

    const int rowA = warp_m * 64 + (lane & 15);
    const int rowW = warp_n * 64 + (lane & 7) + ((lane >> 3) & 1) * 8;
    const int koff = (lane >> 4) * 8;

    for (int kt = 0; kt < NTILES; ++kt) {
        const int s = kt % STAGES;
        asm volatile("cp.async.wait_group 1;" ::: "memory");
        __syncthreads();
        issue(kt + 2);

        const uint32_t bA = sbase + (uint32_t)(s * STAGE_H) * 2;
        const uint32_t bW = bA + (uint32_t)(A_ROWS * SSTR) * 2;
#pragma unroll
        for (int ks = 0; ks < 4; ++ks) {
            const int kb = ks * 16 + koff;
            uint32_t af[4][4], bf[8][2];
#pragma unroll
            for (int mf = 0; mf < 4; ++mf)
                ldmx4(bA + (uint32_t)((rowA + mf * 16) * SSTR + kb) * 2,
                      af[mf][0], af[mf][1], af[mf][2], af[mf][3]);
#pragma unroll
            for (int nf2 = 0; nf2 < 4; ++nf2) {
                uint32_t r0, r1, r2, r3;
                ldmx4(bW + (uint32_t)((rowW + nf2 * 16) * SSTR + kb) * 2, r0, r1, r2, r3);
                bf[nf2 * 2 + 0][0] = r0; bf[nf2 * 2 + 0][1] = r2;
                bf[nf2 * 2 + 1][0] = r1; bf[nf2 * 2 + 1][1] = r3;
            }
#pragma unroll
            for (int mf = 0; mf < 4; ++mf)
#pragma unroll
                for (int nf = 0; nf < 8; ++nf)
                    mma16816(acc[mf][nf], af[mf], bf[nf]);
        }
    }

    const int g = lane >> 2, t4 = lane & 3;
#pragma unroll
    for (int mf = 0; mf < 4; ++mf) {
#pragma unroll
        for (int nf = 0; nf < 8; ++nf) {
            int m = bm * 256 + warp_m * 64 + mf * 16 + g;
            int n = bn * 128 + warp_n * 64 + nf * 8 + t4 * 2;
            *reinterpret_cast<float2*>(out + (size_t)m * OUT_F + n) =
                make_float2(acc[mf][nf][0], acc[mf][nf][1]);
            *reinterpret_cast<float2*>(out + (size_t)(m + 8) * OUT_F + n) =
                make_float2(acc[mf][nf][2], acc[mf][nf][3]);
        }
    }
}

// ---------------- launch ----------------
extern "C" void kernel_launch(void* const* d_in, const int* in_sizes, int n_in,
                              void* d_out, int out_size)
{
    const float* x  = nullptr;
    const void*  wq = nullptr;
    const float* ws = nullptr;
    const float* la = nullptr;
    const float* lb = nullptr;

    int lora_seen = 0;
    for (int i = 0; i < n_in; ++i) {
        long n = (long)in_sizes[i];
        if (n == 33554432L)      x  = (const float*)d_in[i];
        else if (n == 16777216L) wq = d_in[i];
        else if (n == 1L)        ws = (const float*)d_in[i];
        else if (n == 262144L) {
            if (lora_seen++ == 0) la = (const float*)d_in[i];
            else                  lb = (const float*)d_in[i];
        }
    }
    float* out = (float*)d_out;

    cudaFuncSetAttribute(qlora_mma_kernel,
                         cudaFuncAttributeMaxDynamicSharedMemorySize, SMEM_MAIN);

    prep_kernel<<<TB + XB + WB + BB, 128>>>(x, wq, la, lb, ws);
    qlora_mma_kernel<<<dim3(OUT_F / 128, M_TOTAL / 256), 256, SMEM_MAIN>>>(out);
}

// round 17
// speedup vs baseline: 1.0612x; 1.0612x over previous
#include <cuda_runtime.h>
#include <cuda_fp16.h>
#include <cstdint>

#define IN_F   4096
#define OUT_F  4096
#define LORA_R 64
#define M_TOTAL 8192

// ---------------- device scratch ----------------
__device__ __half g_xf[(size_t)M_TOTAL * IN_F];    // fp16(s*x)  64 MB
__device__ __half g_wf[(size_t)OUT_F * IN_F];      // fp16(Wq)   32 MB (exact)
__device__ __half g_af[(size_t)LORA_R * IN_F];     // fp16(lora_A)
__device__ __half g_bf[(size_t)OUT_F * LORA_R];    // fp16(lora_B)
__device__ __half g_t[(size_t)M_TOTAL * LORA_R];   // fp16(0.25 * x @ A^T)

__device__ __forceinline__ uint32_t smem_u32(const void* p) {
    uint32_t a;
    asm("{ .reg .u64 t; cvta.to.shared.u64 t, %1; cvt.u32.u64 %0, t; }" : "=r"(a) : "l"(p));
    return a;
}

// ---------------- kernel 1: fused conversions (R13 proven shape) ----------------
#define XB (M_TOTAL * IN_F / 4 / 256)        // 32768
#define WB (OUT_F * IN_F / 4 / 256)          // 16384
#define ABB (2 * LORA_R * IN_F / 4 / 256)    // 512

__global__ __launch_bounds__(256) void conv_all_kernel(
    const float* __restrict__ x, const void* __restrict__ wqv,
    const float* __restrict__ A, const float* __restrict__ B,
    const float* __restrict__ ws)
{
    const int b = blockIdx.x;
    if (b < XB) {
        const float s = ws[0];
        size_t i = (size_t)b * 256 + threadIdx.x;
        float4 v = reinterpret_cast<const float4*>(x)[i];
        __half2* p = reinterpret_cast<__half2*>(g_xf) + i * 2;
        p[0] = __floats2half2_rn(s * v.x, s * v.y);
        p[1] = __floats2half2_rn(s * v.z, s * v.w);
    } else if (b < XB + WB) {
        __shared__ int s_is_i32;
        size_t i = ((size_t)(b - XB) * 256 + threadIdx.x) * 4;
        int4 q = *reinterpret_cast<const int4*>((const int*)wqv + i);
        bool ok = (q.x >= -8 && q.x <= 7) && (q.y >= -8 && q.y <= 7) &&
                  (q.z >= -8 && q.z <= 7) && (q.w >= -8 && q.w <= 7);
        if (threadIdx.x == 0) s_is_i32 = 1;
        __syncthreads();
        if (!ok) s_is_i32 = 0;
        __syncthreads();
        __half2* p = reinterpret_cast<__half2*>(g_wf + i);
        if (s_is_i32) {
            p[0] = __floats2half2_rn((float)q.x, (float)q.y);
            p[1] = __floats2half2_rn((float)q.z, (float)q.w);
        } else {
            const int8_t* c = (const int8_t*)wqv + i;
            p[0] = __floats2half2_rn((float)c[0], (float)c[1]);
            p[1] = __floats2half2_rn((float)c[2], (float)c[3]);
        }
    } else {
        size_t i = ((size_t)(b - XB - WB) * 256 + threadIdx.x) * 4;
        const size_t NA = (size_t)LORA_R * IN_F;
        if (i < NA) {
            float4 v = *reinterpret_cast<const float4*>(A + i);
            __half2* p = reinterpret_cast<__half2*>(g_af + i);
            p[0] = __floats2half2_rn(v.x, v.y);
            p[1] = __floats2half2_rn(v.z, v.w);
        } else {
            size_t j = i - NA;
            float4 v = *reinterpret_cast<const float4*>(B + j);
            __half2* p = reinterpret_cast<__half2*>(g_bf + j);
            p[0] = __floats2half2_rn(v.x, v.y);
            p[1] = __floats2half2_rn(v.z, v.w);
        }
    }
}

// ---------------- shared mma helpers ----------------
__device__ __forceinline__ void cp16(uint32_t dst, const void* src) {
    asm volatile("cp.async.cg.shared.global [%0], [%1], 16;" :: "r"(dst), "l"(src) : "memory");
}
__device__ __forceinline__ void ldmx4(uint32_t addr, uint32_t& r0, uint32_t& r1,
                                      uint32_t& r2, uint32_t& r3) {
    asm volatile("ldmatrix.sync.aligned.m8n8.x4.shared.b16 {%0,%1,%2,%3}, [%4];"
                 : "=r"(r0), "=r"(r1), "=r"(r2), "=r"(r3) : "r"(addr));
}
__device__ __forceinline__ void mma16816(float* c, const uint32_t* a, const uint32_t* b) {
    asm volatile(
        "mma.sync.aligned.m16n8k16.row.col.f32.f16.f16.f32 "
        "{%0,%1,%2,%3}, {%4,%5,%6,%7}, {%8,%9}, {%0,%1,%2,%3};"
        : "+f"(c[0]), "+f"(c[1]), "+f"(c[2]), "+f"(c[3])
        : "r"(a[0]), "r"(a[1]), "r"(a[2]), "r"(a[3]), "r"(b[0]), "r"(b[1]));
}

// ---------------- kernel 2: t = (0.25/s) * xf @ af^T (R13 proven) ----------------
#define TSTR 40
__global__ __launch_bounds__(128) void t_mma_kernel(const float* __restrict__ ws)
{
    __shared__ __align__(16) __half sm[2][(64 + 64) * TSTR];
    const int tid = threadIdx.x, wid = tid >> 5, lane = tid & 31;
    const int warp_m = wid & 1, warp_n = wid >> 1;
    const int bm = blockIdx.x;

    float acc[2][4][4];
#pragma unroll
    for (int i = 0; i < 2; ++i)
#pragma unroll
        for (int j = 0; j < 4; ++j)
#pragma unroll
            for (int r = 0; r < 4; ++r) acc[i][j][r] = 0.f;

    auto issue = [&](int kt) {
        if (kt < IN_F / 32) {
            const int s = kt & 1;
            const uint32_t dA = smem_u32(&sm[s][0]);
            const uint32_t dW = dA + (uint32_t)(64 * TSTR) * 2;
            const int ko = kt * 32;
#pragma unroll
            for (int u = 0; u < 2; ++u) {
                int c = tid + u * 128;
                int row = c >> 2, kc = (c & 3) * 8;
                cp16(dA + (uint32_t)(row * TSTR + kc) * 2,
                     g_xf + (size_t)(bm * 64 + row) * IN_F + ko + kc);
            }
#pragma unroll
            for (int u = 0; u < 2; ++u) {
                int c = tid + u * 128;
                int row = c >> 2, kc = (c & 3) * 8;
                cp16(dW + (uint32_t)(row * TSTR + kc) * 2,
                     g_af + (size_t)row * IN_F + ko + kc);
            }
        }
        asm volatile("cp.async.commit_group;" ::: "memory");
    };

    issue(0);
    const int rowA = warp_m * 32 + (lane & 15);
    const int rowW = warp_n * 32 + (lane & 7) + ((lane >> 3) & 1) * 8;
    const int koff = (lane >> 4) * 8;

    for (int kt = 0; kt < IN_F / 32; ++kt) {
        const int s = kt & 1;
        issue(kt + 1);
        asm volatile("cp.async.wait_group 1;" ::: "memory");
        __syncthreads();

        const uint32_t bA = smem_u32(&sm[s][0]);
        const uint32_t bW = bA + (uint32_t)(64 * TSTR) * 2;
#pragma unroll
        for (int ks = 0; ks < 2; ++ks) {
            const int kb = ks * 16 + koff;
            uint32_t af[2][4], bf[4][2];
#pragma unroll
            for (int mf = 0; mf < 2; ++mf)
                ldmx4(bA + (uint32_t)((rowA + mf * 16) * TSTR + kb) * 2,
                      af[mf][0], af[mf][1], af[mf][2], af[mf][3]);
#pragma unroll
            for (int nf2 = 0; nf2 < 2; ++nf2) {
                uint32_t r0, r1, r2, r3;
                ldmx4(bW + (uint32_t)((rowW + nf2 * 16) * TSTR + kb) * 2, r0, r1, r2, r3);
                bf[nf2 * 2 + 0][0] = r0; bf[nf2 * 2 + 0][1] = r2;
                bf[nf2 * 2 + 1][0] = r1; bf[nf2 * 2 + 1][1] = r3;
            }
#pragma unroll
            for (int mf = 0; mf < 2; ++mf)
#pragma unroll
                for (int nf = 0; nf < 4; ++nf)
                    mma16816(acc[mf][nf], af[mf], bf[nf]);
        }
        __syncthreads();
    }

    const float sc = 0.25f / ws[0];
    const int g = lane >> 2, t4 = lane & 3;
#pragma unroll
    for (int mf = 0; mf < 2; ++mf)
#pragma unroll
        for (int nf = 0; nf < 4; ++nf) {
            int m = bm * 64 + warp_m * 32 + mf * 16 + g;
            int n = warp_n * 32 + nf * 8 + t4 * 2;
            *reinterpret_cast<__half2*>(g_t + (size_t)m * LORA_R + n) =
                __floats2half2_rn(sc * acc[mf][nf][0], sc * acc[mf][nf][1]);
            *reinterpret_cast<__half2*>(g_t + (size_t)(m + 8) * LORA_R + n) =
                __floats2half2_rn(sc * acc[mf][nf][2], sc * acc[mf][nf][3]);
        }
}

// ---------------- kernel 3: main fp16 mma GEMM — 512 threads, 16 warps ----------
// CTA 256(M) x 128(N), BK=64, 3-stage ring, warps 4m x 4n, warp tile 64x32.
#define SSTR 72
#define NTILES (IN_F / 64 + 1)           // 65
#define A_ROWS 256
#define W_ROWS 128
#define STAGE_H ((A_ROWS + W_ROWS) * SSTR)
#define STAGES 3
#define SMEM_MAIN (STAGES * STAGE_H * 2)  // 165888 B

__global__ __launch_bounds__(512, 1) void qlora_mma_kernel(float* __restrict__ out)
{
    extern __shared__ __align__(16) __half smem[];

    const int tid  = threadIdx.x;
    const int wid  = tid >> 5;
    const int lane = tid & 31;
    const int warp_m = wid & 3;      // 0..3 (64 rows each)
    const int warp_n = wid >> 2;     // 0..3 (32 cols each)
    const int bm = blockIdx.y, bn = blockIdx.x;
    const uint32_t sbase = smem_u32(smem);

    float acc[4][4][4];
#pragma unroll
    for (int i = 0; i < 4; ++i)
#pragma unroll
        for (int j = 0; j < 4; ++j)
#pragma unroll
            for (int r = 0; r < 4; ++r) acc[i][j][r] = 0.f;

    auto issue = [&](int kt) {
        if (kt < NTILES) {
            const int s = kt % STAGES;
            const __half *aSrc, *wSrc;
            int lda, ko;
            if (kt < IN_F / 64) { aSrc = g_xf; wSrc = g_wf; lda = IN_F;   ko = kt * 64; }
            else                { aSrc = g_t;  wSrc = g_bf; lda = LORA_R; ko = 0; }
            const __half* aBase = aSrc + (size_t)(bm * A_ROWS) * lda + ko;
            const __half* wBase = wSrc + (size_t)(bn * W_ROWS) * lda + ko;
            const uint32_t dA = sbase + (uint32_t)(s * STAGE_H) * 2;
            const uint32_t dW = dA + (uint32_t)(A_ROWS * SSTR) * 2;
#pragma unroll
            for (int u = 0; u < 4; ++u) {          // A: 2048 chunks / 512 thr
                int c = tid + u * 512;
                int row = c >> 3, kc = (c & 7) * 8;
                cp16(dA + (uint32_t)(row * SSTR + kc) * 2, aBase + (size_t)row * lda + kc);
            }
#pragma unroll
            for (int u = 0; u < 2; ++u) {          // W: 1024 chunks
                int c = tid + u * 512;
                int row = c >> 3, kc = (c & 7) * 8;
                cp16(dW + (uint32_t)(row * SSTR + kc) * 2, wBase + (size_t)row * lda + kc);
            }
        }
        asm volatile("cp.async.commit_group;" ::: "memory");
    };

    issue(0); issue(1);

    const int rowA = warp_m * 64 + (lane & 15);
    const int rowW = warp_n * 32 + (lane & 7) + ((lane >> 3) & 1) * 8;
    const int koff = (lane >> 4) * 8;

    for (int kt = 0; kt < NTILES; ++kt) {
        const int s = kt % STAGES;
        asm volatile("cp.async.wait_group 1;" ::: "memory");
        __syncthreads();
        issue(kt + 2);

        const uint32_t bA = sbase + (uint32_t)(s * STAGE_H) * 2;
        const uint32_t bW = bA + (uint32_t)(A_ROWS * SSTR) * 2;
#pragma unroll
        for (int ks = 0; ks < 4; ++ks) {
            const int kb = ks * 16 + koff;
            uint32_t af[4][4], bf[4][2];
#pragma unroll
            for (int mf = 0; mf < 4; ++mf)
                ldmx4(bA + (uint32_t)((rowA + mf * 16) * SSTR + kb) * 2,
                      af[mf][0], af[mf][1], af[mf][2], af[mf][3]);
#pragma unroll
            for (int nf2 = 0; nf2 < 2; ++nf2) {
                uint32_t r0, r1, r2, r3;
                ldmx4(bW + (uint32_t)((rowW + nf2 * 16) * SSTR + kb) * 2, r0, r1, r2, r3);
                bf[nf2 * 2 + 0][0] = r0; bf[nf2 * 2 + 0][1] = r2;
                bf[nf2 * 2 + 1][0] = r1; bf[nf2 * 2 + 1][1] = r3;
            }
#pragma unroll
            for (int mf = 0; mf < 4; ++mf)
#pragma unroll
                for (int nf = 0; nf < 4; ++nf)
                    mma16816(acc[mf][nf], af[mf], bf[nf]);
        }
    }

    const int g = lane >> 2, t4 = lane & 3;
#pragma unroll
    for (int mf = 0; mf < 4; ++mf) {
#pragma unroll
        for (int nf = 0; nf < 4; ++nf) {
            int m = bm * 256 + warp_m * 64 + mf * 16 + g;
            int n = bn * 128 + warp_n * 32 + nf * 8 + t4 * 2;
            *reinterpret_cast<float2*>(out + (size_t)m * OUT_F + n) =
                make_float2(acc[mf][nf][0], acc[mf][nf][1]);
            *reinterpret_cast<float2*>(out + (size_t)(m + 8) * OUT_F + n) =
                make_float2(acc[mf][nf][2], acc[mf][nf][3]);
        }
    }
}

// ---------------- launch ----------------
extern "C" void kernel_launch(void* const* d_in, const int* in_sizes, int n_in,
                              void* d_out, int out_size)
{
    const float* x  = nullptr;
    const void*  wq = nullptr;
    const float* ws = nullptr;
    const float* la = nullptr;
    const float* lb = nullptr;

    int lora_seen = 0;
    for (int i = 0; i < n_in; ++i) {
        long n = (long)in_sizes[i];
        if (n == 33554432L)      x  = (const float*)d_in[i];
        else if (n == 16777216L) wq = d_in[i];
        else if (n == 1L)        ws = (const float*)d_in[i];
        else if (n == 262144L) {
            if (lora_seen++ == 0) la = (const float*)d_in[i];
            else                  lb = (const float*)d_in[i];
        }
    }
    float* out = (float*)d_out;

    cudaFuncSetAttribute(qlora_mma_kernel,
                         cudaFuncAttributeMaxDynamicSharedMemorySize, SMEM_MAIN);

    conv_all_kernel<<<XB + WB + ABB, 256>>>(x, wq, la, lb, ws);
    t_mma_kernel<<<M_TOTAL / 64, 128>>>(ws);
    qlora_mma_kernel<<<dim3(OUT_F / 128, M_TOTAL / 256), 512, SMEM_MAIN>>>(out);
}